// round 5
// baseline (speedup 1.0000x reference)
#include <cuda_runtime.h>
#include <cstdint>

// Chamfer distance via exact grid nearest-neighbor search.
// pred/gt: [4, 8192, 3] fp32, N(0,1). Output: scalar fp32.
//
// Brute force is fma-pipe-floor-limited (~71us on sm_103a: FFMA2 rt=3 from
// register banking). Instead: bin each point set into a 64^3 uniform grid
// (CSR layout), then each query does an expanding Chebyshev-ring search with
// the exact bound "any point in ring r is >= (r-1)*h away". ~5M pair evals
// instead of 537M. Exact result: min is order-independent.
//
// R4 fix: g_start rows padded to GB3+4 so every per-grid row is 16B-aligned
// (GB3+1 broke int4 stores for grids >= 1 -> misaligned address trap).

#define NPTS   8192
#define BATCH  4
#define NGRIDS 8                    // batch x {pred,gt}
#define GB     64
#define GB3    (GB * GB * GB)       // 262144
#define SROW   (GB3 + 4)            // start-row stride, multiple of 4
#define XMIN   (-6.0f)
#define GH     (12.0f / GB)         // 0.1875 (exactly representable)
#define INVH   (GB / 12.0f)
#define NQ     (2 * BATCH * NPTS)   // 65536 queries
#define CHUNK  (GB3 / 1024)         // 256 cells per scan thread

__device__ int    g_cnt[NGRIDS][GB3];
__device__ int    g_start[NGRIDS][SROW];
__device__ int    g_cursor[NGRIDS][GB3];
__device__ float4 g_pts[NGRIDS][NPTS];
__device__ float  g_minq[NQ];

__device__ __forceinline__ int bin1(float v) {
    int c = (int)floorf((v - XMIN) * INVH);
    return min(GB - 1, max(0, c));
}

// ---- K1: zero the cell counters (must run every replay) ----
__global__ void cd_zero() {
    int i = blockIdx.x * blockDim.x + threadIdx.x;
    if (i < (int)(sizeof(g_cnt) / sizeof(int4)))
        ((int4*)g_cnt)[i] = make_int4(0, 0, 0, 0);
}

// ---- K2: count points per cell ----
__global__ void cd_count(const float* __restrict__ pred, const float* __restrict__ gt) {
    int t = blockIdx.x * blockDim.x + threadIdx.x;   // 65536 = 8 grids x 8192
    int i = t & (NPTS - 1);
    int gidx = t >> 13;                              // (b<<1)|s
    int s = gidx & 1, b = gidx >> 1;
    const float* p = (s == 0 ? pred : gt) + ((size_t)b * NPTS + i) * 3;
    int cx = bin1(p[0]), cy = bin1(p[1]), cz = bin1(p[2]);
    atomicAdd(&g_cnt[gidx][(cz * GB + cy) * GB + cx], 1);
}

// ---- K3: exclusive scan per grid -> CSR starts + scatter cursors ----
__global__ void cd_scan() {
    __shared__ int sh[1024];
    const int g = blockIdx.x;
    const int tid = threadIdx.x;
    const int4* cnt4 = (const int4*)&g_cnt[g][tid * CHUNK];

    int s = 0;
    #pragma unroll 8
    for (int k = 0; k < CHUNK / 4; k++) {
        int4 c = cnt4[k];
        s += c.x + c.y + c.z + c.w;
    }
    sh[tid] = s;
    __syncthreads();
    // Hillis-Steele inclusive scan over 1024 thread sums
    #pragma unroll
    for (int off = 1; off < 1024; off <<= 1) {
        int v = (tid >= off) ? sh[tid - off] : 0;
        __syncthreads();
        sh[tid] += v;
        __syncthreads();
    }
    int run = (tid > 0) ? sh[tid - 1] : 0;

    int4* st4 = (int4*)&g_start[g][tid * CHUNK];   // SROW % 4 == 0 -> aligned
    int4* cu4 = (int4*)&g_cursor[g][tid * CHUNK];
    #pragma unroll 4
    for (int k = 0; k < CHUNK / 4; k++) {
        int4 c = cnt4[k];
        int4 o;
        o.x = run;
        o.y = o.x + c.x;
        o.z = o.y + c.y;
        o.w = o.z + c.z;
        run = o.w + c.w;
        st4[k] = o;
        cu4[k] = o;
    }
    if (tid == 1023) g_start[g][GB3] = run;   // == NPTS
}

// ---- K4: scatter points into CSR slots (xyz + pad) ----
__global__ void cd_scatter(const float* __restrict__ pred, const float* __restrict__ gt) {
    int t = blockIdx.x * blockDim.x + threadIdx.x;
    int i = t & (NPTS - 1);
    int gidx = t >> 13;
    int s = gidx & 1, b = gidx >> 1;
    const float* p = (s == 0 ? pred : gt) + ((size_t)b * NPTS + i) * 3;
    float x = p[0], y = p[1], z = p[2];
    int cx = bin1(x), cy = bin1(y), cz = bin1(z);
    int pos = atomicAdd(&g_cursor[gidx][(cz * GB + cy) * GB + cx], 1);
    g_pts[gidx][pos] = make_float4(x, y, z, 0.0f);
}

// ---- K5: expanding-ring exact NN per query ----
__global__ __launch_bounds__(128)
void cd_query(const float* __restrict__ pred, const float* __restrict__ gt) {
    int t = blockIdx.x * blockDim.x + threadIdx.x;   // 65536
    int i = t & (NPTS - 1);
    int b = (t >> 13) & (BATCH - 1);
    int dir = t >> 15;                               // 0: pred->gt, 1: gt->pred

    const float* qp = (dir == 0 ? pred : gt) + ((size_t)b * NPTS + i) * 3;
    const int gidx = (b << 1) | (dir == 0 ? 1 : 0);  // database grid
    const float qx = qp[0], qy = qp[1], qz = qp[2];
    const int cx = bin1(qx), cy = bin1(qy), cz = bin1(qz);

    const int*    start = g_start[gidx];
    const float4* pts   = g_pts[gidx];

    float best = __int_as_float(0x7F800000);

    auto scan_cell = [&](int ix, int iy, int iz) {
        if ((unsigned)ix >= GB || (unsigned)iy >= GB || (unsigned)iz >= GB) return;
        int c = (iz * GB + iy) * GB + ix;
        int s = __ldg(&start[c]);
        int e = __ldg(&start[c + 1]);
        for (int k = s; k < e; k++) {
            float4 p = pts[k];
            float dx = qx - p.x, dy = qy - p.y, dz = qz - p.z;
            float d = fmaf(dx, dx, fmaf(dy, dy, dz * dz));
            best = fminf(best, d);
        }
    };

    for (int r = 0; r < GB; r++) {
        if (r >= 2) {
            float rb = (float)(r - 1) * GH;          // exact: (r-1)*3/16
            if (best <= rb * rb) break;              // ring r points are >= rb away
        }
        if (r == 0) {
            scan_cell(cx, cy, cz);
        } else {
            // z faces (full squares)
            for (int dy = -r; dy <= r; dy++)
                for (int dx = -r; dx <= r; dx++) {
                    scan_cell(cx + dx, cy + dy, cz - r);
                    scan_cell(cx + dx, cy + dy, cz + r);
                }
            // y faces and x faces (interior z band)
            for (int dz = -r + 1; dz <= r - 1; dz++) {
                for (int dx = -r; dx <= r; dx++) {
                    scan_cell(cx + dx, cy - r, cz + dz);
                    scan_cell(cx + dx, cy + r, cz + dz);
                }
                for (int dy = -r + 1; dy <= r - 1; dy++) {
                    scan_cell(cx - r, cy + dy, cz + dz);
                    scan_cell(cx + r, cy + dy, cz + dz);
                }
            }
        }
    }

    g_minq[t] = best;
}

// ---- K6: sum all mins -> scalar ----
__global__ void cd_reduce(float* __restrict__ out) {
    __shared__ float warp_sums[32];
    const int tid = threadIdx.x;
    float s = 0.0f;
    for (int i = tid; i < NQ; i += 1024)
        s += g_minq[i];
    #pragma unroll
    for (int off = 16; off > 0; off >>= 1)
        s += __shfl_down_sync(0xFFFFFFFFu, s, off);
    if ((tid & 31) == 0) warp_sums[tid >> 5] = s;
    __syncthreads();
    if (tid < 32) {
        float v = warp_sums[tid];
        #pragma unroll
        for (int off = 16; off > 0; off >>= 1)
            v += __shfl_down_sync(0xFFFFFFFFu, v, off);
        if (tid == 0)
            out[0] = v / (float)(BATCH * NPTS);  // mean_n + mean_m share denom 32768
    }
}

extern "C" void kernel_launch(void* const* d_in, const int* in_sizes, int n_in,
                              void* d_out, int out_size) {
    const float* pred = (const float*)d_in[0];
    const float* gt   = (const float*)d_in[1];
    float* out        = (float*)d_out;

    cd_zero<<<512, 1024>>>();                    // 524288 int4
    cd_count<<<64, 1024>>>(pred, gt);            // 65536
    cd_scan<<<NGRIDS, 1024>>>();                 // 8 blocks
    cd_scatter<<<64, 1024>>>(pred, gt);          // 65536
    cd_query<<<NQ / 128, 128>>>(pred, gt);       // 512 blocks x 128
    cd_reduce<<<1, 1024>>>(out);
}

// round 6
// speedup vs baseline: 9.1278x; 9.1278x over previous
#include <cuda_runtime.h>
#include <cstdint>

// Chamfer distance via exact grid nearest-neighbor search (row-merged CSR).
// pred/gt: [4, 8192, 3] fp32, N(0,1). Output: scalar fp32.
//
// R5 lesson: 64^3 cells + per-cell scans = thousands of serial L2 round trips
// for tail queries (1085us). Now: 32^3 grid (h=0.375, ~1-27 pts/cell), CSR
// with x-fastest cell order so each (y,z) x-run of cells is CONTIGUOUS in
// CSR -> one (s,e) descriptor per row. The common radius-1 cube (9 rows) has
// all 18 descriptor loads batched (MLP=18, one L2 latency), then streams
// contiguous float4 points. ~98% of queries stop after radius 1
// (bound: unscanned cells hold points >= r*h away; best ~0.006 << 0.14).

#define NPTS   8192
#define BATCH  4
#define NGRIDS 8                    // batch x {pred,gt}
#define GB     32
#define GB3    (GB * GB * GB)       // 32768
#define SROW   (GB3 + 4)            // start-row stride, multiple of 4 (16B align)
#define XMIN   (-6.0f)
#define INVH   (GB / 12.0f)         // 2.6666667f
#define RBSAFE 0.37495f             // slightly < 1/INVH: conservative break bound
#define NQ     (2 * BATCH * NPTS)   // 65536 queries
#define CHUNK  (GB3 / 1024)         // 32 cells per scan thread

__device__ int    g_cnt[NGRIDS][GB3];
__device__ int    g_start[NGRIDS][SROW];
__device__ int    g_cursor[NGRIDS][GB3];
__device__ float4 g_pts[NGRIDS][NPTS];
__device__ float  g_minq[NQ];

__device__ __forceinline__ int bin1(float v) {
    int c = (int)floorf((v - XMIN) * INVH);
    return min(GB - 1, max(0, c));
}

// ---- K1: zero the cell counters (must run every replay) ----
__global__ void cd_zero() {
    int i = blockIdx.x * blockDim.x + threadIdx.x;   // 65536 int4 slots
    if (i < (int)(sizeof(g_cnt) / sizeof(int4)))
        ((int4*)g_cnt)[i] = make_int4(0, 0, 0, 0);
}

// ---- K2: count points per cell ----
__global__ void cd_count(const float* __restrict__ pred, const float* __restrict__ gt) {
    int t = blockIdx.x * blockDim.x + threadIdx.x;   // 65536 = 8 grids x 8192
    int i = t & (NPTS - 1);
    int gidx = t >> 13;                              // (b<<1)|s
    int s = gidx & 1, b = gidx >> 1;
    const float* p = (s == 0 ? pred : gt) + ((size_t)b * NPTS + i) * 3;
    int cx = bin1(p[0]), cy = bin1(p[1]), cz = bin1(p[2]);
    atomicAdd(&g_cnt[gidx][(cz * GB + cy) * GB + cx], 1);
}

// ---- K3: exclusive scan per grid -> CSR starts + scatter cursors ----
__global__ void cd_scan() {
    __shared__ int sh[1024];
    const int g = blockIdx.x;
    const int tid = threadIdx.x;
    const int4* cnt4 = (const int4*)&g_cnt[g][tid * CHUNK];

    int s = 0;
    #pragma unroll
    for (int k = 0; k < CHUNK / 4; k++) {
        int4 c = cnt4[k];
        s += c.x + c.y + c.z + c.w;
    }
    sh[tid] = s;
    __syncthreads();
    // Hillis-Steele inclusive scan over 1024 thread sums
    #pragma unroll
    for (int off = 1; off < 1024; off <<= 1) {
        int v = (tid >= off) ? sh[tid - off] : 0;
        __syncthreads();
        sh[tid] += v;
        __syncthreads();
    }
    int run = (tid > 0) ? sh[tid - 1] : 0;

    int4* st4 = (int4*)&g_start[g][tid * CHUNK];     // SROW % 4 == 0 -> aligned
    int4* cu4 = (int4*)&g_cursor[g][tid * CHUNK];
    #pragma unroll
    for (int k = 0; k < CHUNK / 4; k++) {
        int4 c = cnt4[k];
        int4 o;
        o.x = run;
        o.y = o.x + c.x;
        o.z = o.y + c.y;
        o.w = o.z + c.z;
        run = o.w + c.w;
        st4[k] = o;
        cu4[k] = o;
    }
    if (tid == 1023) g_start[g][GB3] = run;          // == NPTS
}

// ---- K4: scatter points into CSR slots (xyz + pad) ----
__global__ void cd_scatter(const float* __restrict__ pred, const float* __restrict__ gt) {
    int t = blockIdx.x * blockDim.x + threadIdx.x;
    int i = t & (NPTS - 1);
    int gidx = t >> 13;
    int s = gidx & 1, b = gidx >> 1;
    const float* p = (s == 0 ? pred : gt) + ((size_t)b * NPTS + i) * 3;
    float x = p[0], y = p[1], z = p[2];
    int cx = bin1(x), cy = bin1(y), cz = bin1(z);
    int pos = atomicAdd(&g_cursor[gidx][(cz * GB + cy) * GB + cx], 1);
    g_pts[gidx][pos] = make_float4(x, y, z, 0.0f);
}

// ---- K5: exact NN per query, row-merged cube scans ----
__global__ __launch_bounds__(256)
void cd_query(const float* __restrict__ pred, const float* __restrict__ gt) {
    int t = blockIdx.x * blockDim.x + threadIdx.x;   // 65536
    int i = t & (NPTS - 1);
    int b = (t >> 13) & (BATCH - 1);
    int dir = t >> 15;                               // 0: pred->gt, 1: gt->pred

    const float* qp = (dir == 0 ? pred : gt) + ((size_t)b * NPTS + i) * 3;
    const int gidx = (b << 1) | (dir == 0 ? 1 : 0);  // database grid
    const float qx = qp[0], qy = qp[1], qz = qp[2];
    const int cx = bin1(qx), cy = bin1(qy), cz = bin1(qz);

    const int*    start = g_start[gidx];
    const float4* pts   = g_pts[gidx];

    float best = __int_as_float(0x7F800000);

    // ---- phase 1: radius-1 cube as 9 x-rows, descriptors prefetched ----
    {
        const int xa = max(cx - 1, 0);
        const int xb = min(cx + 1, GB - 1);
        int s_[9], e_[9];
        #pragma unroll
        for (int j = 0; j < 9; j++) {
            int z = cz + (j / 3) - 1;
            int y = cy + (j % 3) - 1;
            bool ok = ((unsigned)z < GB) & ((unsigned)y < GB);
            int base = (z * GB + y) * GB;
            s_[j] = ok ? __ldg(&start[base + xa])     : 0;
            e_[j] = ok ? __ldg(&start[base + xb + 1]) : 0;
        }
        #pragma unroll
        for (int j = 0; j < 9; j++) {
            for (int k = s_[j]; k < e_[j]; k++) {
                float4 p = pts[k];
                float dx = qx - p.x, dy = qy - p.y, dz = qz - p.z;
                float d = fmaf(dx, dx, fmaf(dy, dy, dz * dz));
                best = fminf(best, d);
            }
        }
    }

    // ---- phase 2 (rare, ~2% of queries): expand cube until bound holds ----
    int r = 1;
    float rb = RBSAFE;                               // r * RBSAFE
    while (best > rb * rb && r < GB) {
        r++;
        rb = (float)r * RBSAFE;
        const int z0 = max(cz - r, 0), z1 = min(cz + r, GB - 1);
        const int y0 = max(cy - r, 0), y1 = min(cy + r, GB - 1);
        const int xa = max(cx - r, 0), xb = min(cx + r, GB - 1);
        for (int z = z0; z <= z1; z++) {
            for (int y = y0; y <= y1; y++) {
                int base = (z * GB + y) * GB;
                int s = __ldg(&start[base + xa]);
                int e = __ldg(&start[base + xb + 1]);
                for (int k = s; k < e; k++) {
                    float4 p = pts[k];
                    float dx = qx - p.x, dy = qy - p.y, dz = qz - p.z;
                    float d = fmaf(dx, dx, fmaf(dy, dy, dz * dz));
                    best = fminf(best, d);
                }
            }
        }
    }

    g_minq[t] = best;
}

// ---- K6: sum all mins -> scalar (single block: deterministic) ----
__global__ void cd_reduce(float* __restrict__ out) {
    __shared__ float warp_sums[32];
    const int tid = threadIdx.x;
    const float4* m4 = (const float4*)g_minq;
    float s = 0.0f;
    for (int i = tid; i < NQ / 4; i += 1024) {
        float4 v = m4[i];
        s += (v.x + v.y) + (v.z + v.w);
    }
    #pragma unroll
    for (int off = 16; off > 0; off >>= 1)
        s += __shfl_down_sync(0xFFFFFFFFu, s, off);
    if ((tid & 31) == 0) warp_sums[tid >> 5] = s;
    __syncthreads();
    if (tid < 32) {
        float v = warp_sums[tid];
        #pragma unroll
        for (int off = 16; off > 0; off >>= 1)
            v += __shfl_down_sync(0xFFFFFFFFu, v, off);
        if (tid == 0)
            out[0] = v / (float)(BATCH * NPTS);      // mean_n + mean_m share denom
    }
}

extern "C" void kernel_launch(void* const* d_in, const int* in_sizes, int n_in,
                              void* d_out, int out_size) {
    const float* pred = (const float*)d_in[0];
    const float* gt   = (const float*)d_in[1];
    float* out        = (float*)d_out;

    cd_zero<<<64, 1024>>>();                     // 65536 int4 (1 MB)
    cd_count<<<64, 1024>>>(pred, gt);            // 65536 threads
    cd_scan<<<NGRIDS, 1024>>>();                 // 8 blocks
    cd_scatter<<<64, 1024>>>(pred, gt);          // 65536 threads
    cd_query<<<NQ / 256, 256>>>(pred, gt);       // 256 blocks x 256
    cd_reduce<<<1, 1024>>>(out);
}

// round 7
// speedup vs baseline: 11.2725x; 1.2350x over previous
#include <cuda_runtime.h>
#include <cstdint>

// Chamfer distance via exact grid NN search, cell-coherent query order.
// pred/gt: [4, 8192, 3] fp32, N(0,1). Output: scalar fp32.
//
// R6 lesson: random query order made every cube scan a scattered wavefront
// per lane (~64us of L1tex traffic for ~2us of math). Chamfer needs only the
// SUM of per-query mins, and the CSR scatter g_pts is already a cell-sorted
// copy of each point set -> query straight out of g_pts. Warp lanes then hold
// spatially adjacent queries; descriptor + point loads are warp-broadcast L1
// hits and phase-2 expansion is warp-coherent.
//
// Grid 32^3 (h=0.375), CSR x-fastest so an x-run of cells is one contiguous
// (s,e) span; radius-1 cube = 9 spans, 18 descriptor loads batched (MLP=18).
// Exact: unscanned cells at Chebyshev radius r hold points >= r*h away;
// RBSAFE < h guards fp rounding. Min is order-independent -> exact result.

#define NPTS   8192
#define BATCH  4
#define NGRIDS 8                    // batch x {pred,gt}
#define GB     32
#define GB3    (GB * GB * GB)       // 32768
#define SROW   (GB3 + 4)            // start-row stride, multiple of 4 (16B align)
#define XMIN   (-6.0f)
#define INVH   (GB / 12.0f)         // 2.6666667f
#define RBSAFE 0.37495f             // slightly < 1/INVH: conservative break bound
#define NQ     (2 * BATCH * NPTS)   // 65536 queries
#define CHUNK  (GB3 / 1024)         // 32 cells per scan thread

__device__ int    g_cnt[NGRIDS][GB3];
__device__ int    g_start[NGRIDS][SROW];
__device__ int    g_cursor[NGRIDS][GB3];
__device__ float4 g_pts[NGRIDS][NPTS];
__device__ float  g_minq[NQ];

__device__ __forceinline__ int bin1(float v) {
    int c = (int)floorf((v - XMIN) * INVH);
    return min(GB - 1, max(0, c));
}

// ---- K1: zero the cell counters (must run every replay) ----
__global__ void cd_zero() {
    int i = blockIdx.x * blockDim.x + threadIdx.x;   // 65536 int4 slots
    if (i < (int)(sizeof(g_cnt) / sizeof(int4)))
        ((int4*)g_cnt)[i] = make_int4(0, 0, 0, 0);
}

// ---- K2: count points per cell ----
__global__ void cd_count(const float* __restrict__ pred, const float* __restrict__ gt) {
    int t = blockIdx.x * blockDim.x + threadIdx.x;   // 65536 = 8 grids x 8192
    int i = t & (NPTS - 1);
    int gidx = t >> 13;                              // (b<<1)|s
    int s = gidx & 1, b = gidx >> 1;
    const float* p = (s == 0 ? pred : gt) + ((size_t)b * NPTS + i) * 3;
    int cx = bin1(p[0]), cy = bin1(p[1]), cz = bin1(p[2]);
    atomicAdd(&g_cnt[gidx][(cz * GB + cy) * GB + cx], 1);
}

// ---- K3: exclusive scan per grid -> CSR starts + scatter cursors ----
__global__ void cd_scan() {
    __shared__ int sh[1024];
    const int g = blockIdx.x;
    const int tid = threadIdx.x;
    const int4* cnt4 = (const int4*)&g_cnt[g][tid * CHUNK];

    int s = 0;
    #pragma unroll
    for (int k = 0; k < CHUNK / 4; k++) {
        int4 c = cnt4[k];
        s += c.x + c.y + c.z + c.w;
    }
    sh[tid] = s;
    __syncthreads();
    #pragma unroll
    for (int off = 1; off < 1024; off <<= 1) {
        int v = (tid >= off) ? sh[tid - off] : 0;
        __syncthreads();
        sh[tid] += v;
        __syncthreads();
    }
    int run = (tid > 0) ? sh[tid - 1] : 0;

    int4* st4 = (int4*)&g_start[g][tid * CHUNK];     // SROW % 4 == 0 -> aligned
    int4* cu4 = (int4*)&g_cursor[g][tid * CHUNK];
    #pragma unroll
    for (int k = 0; k < CHUNK / 4; k++) {
        int4 c = cnt4[k];
        int4 o;
        o.x = run;
        o.y = o.x + c.x;
        o.z = o.y + c.y;
        o.w = o.z + c.z;
        run = o.w + c.w;
        st4[k] = o;
        cu4[k] = o;
    }
    if (tid == 1023) g_start[g][GB3] = run;          // == NPTS
}

// ---- K4: scatter points into CSR slots (xyz + pad) ----
__global__ void cd_scatter(const float* __restrict__ pred, const float* __restrict__ gt) {
    int t = blockIdx.x * blockDim.x + threadIdx.x;
    int i = t & (NPTS - 1);
    int gidx = t >> 13;
    int s = gidx & 1, b = gidx >> 1;
    const float* p = (s == 0 ? pred : gt) + ((size_t)b * NPTS + i) * 3;
    float x = p[0], y = p[1], z = p[2];
    int cx = bin1(x), cy = bin1(y), cz = bin1(z);
    int pos = atomicAdd(&g_cursor[gidx][(cz * GB + cy) * GB + cx], 1);
    g_pts[gidx][pos] = make_float4(x, y, z, 0.0f);
}

// ---- K5: exact NN per query, queries read in cell-sorted order ----
__global__ __launch_bounds__(256)
void cd_query() {
    int t = blockIdx.x * blockDim.x + threadIdx.x;   // 65536
    int i = t & (NPTS - 1);                          // sorted-order index
    int b = (t >> 13) & (BATCH - 1);
    int dir = t >> 15;                               // 0: pred->gt, 1: gt->pred

    const int qgidx = (b << 1) | dir;                // query-side grid (sorted copy)
    const int gidx  = (b << 1) | (dir ^ 1);          // database grid

    float4 qv = g_pts[qgidx][i];
    const float qx = qv.x, qy = qv.y, qz = qv.z;
    const int cx = bin1(qx), cy = bin1(qy), cz = bin1(qz);

    const int*    start = g_start[gidx];
    const float4* pts   = g_pts[gidx];

    float best = __int_as_float(0x7F800000);

    // ---- phase 1: radius-1 cube as 9 x-rows, descriptors prefetched ----
    {
        const int xa = max(cx - 1, 0);
        const int xb = min(cx + 1, GB - 1);
        int s_[9], e_[9];
        #pragma unroll
        for (int j = 0; j < 9; j++) {
            int z = cz + (j / 3) - 1;
            int y = cy + (j % 3) - 1;
            bool ok = ((unsigned)z < GB) & ((unsigned)y < GB);
            int base = (z * GB + y) * GB;
            s_[j] = ok ? __ldg(&start[base + xa])     : 0;
            e_[j] = ok ? __ldg(&start[base + xb + 1]) : 0;
        }
        #pragma unroll
        for (int j = 0; j < 9; j++) {
            for (int k = s_[j]; k < e_[j]; k++) {
                float4 p = pts[k];
                float dx = qx - p.x, dy = qy - p.y, dz = qz - p.z;
                float d = fmaf(dx, dx, fmaf(dy, dy, dz * dz));
                best = fminf(best, d);
            }
        }
    }

    // ---- phase 2 (rare): expand cube until the exact bound holds ----
    int r = 1;
    float rb = RBSAFE;
    while (best > rb * rb && r < GB) {
        r++;
        rb = (float)r * RBSAFE;
        const int z0 = max(cz - r, 0), z1 = min(cz + r, GB - 1);
        const int y0 = max(cy - r, 0), y1 = min(cy + r, GB - 1);
        const int xa = max(cx - r, 0), xb = min(cx + r, GB - 1);
        for (int z = z0; z <= z1; z++) {
            for (int y = y0; y <= y1; y++) {
                int base = (z * GB + y) * GB;
                int s = __ldg(&start[base + xa]);
                int e = __ldg(&start[base + xb + 1]);
                for (int k = s; k < e; k++) {
                    float4 p = pts[k];
                    float dx = qx - p.x, dy = qy - p.y, dz = qz - p.z;
                    float d = fmaf(dx, dx, fmaf(dy, dy, dz * dz));
                    best = fminf(best, d);
                }
            }
        }
    }

    g_minq[t] = best;
}

// ---- K6: sum all mins -> scalar (single block: deterministic) ----
__global__ void cd_reduce(float* __restrict__ out) {
    __shared__ float warp_sums[32];
    const int tid = threadIdx.x;
    const float4* m4 = (const float4*)g_minq;
    float s = 0.0f;
    for (int i = tid; i < NQ / 4; i += 1024) {
        float4 v = m4[i];
        s += (v.x + v.y) + (v.z + v.w);
    }
    #pragma unroll
    for (int off = 16; off > 0; off >>= 1)
        s += __shfl_down_sync(0xFFFFFFFFu, s, off);
    if ((tid & 31) == 0) warp_sums[tid >> 5] = s;
    __syncthreads();
    if (tid < 32) {
        float v = warp_sums[tid];
        #pragma unroll
        for (int off = 16; off > 0; off >>= 1)
            v += __shfl_down_sync(0xFFFFFFFFu, v, off);
        if (tid == 0)
            out[0] = v / (float)(BATCH * NPTS);      // mean_n + mean_m share denom
    }
}

extern "C" void kernel_launch(void* const* d_in, const int* in_sizes, int n_in,
                              void* d_out, int out_size) {
    const float* pred = (const float*)d_in[0];
    const float* gt   = (const float*)d_in[1];
    float* out        = (float*)d_out;

    cd_zero<<<64, 1024>>>();                     // 65536 int4 (1 MB)
    cd_count<<<64, 1024>>>(pred, gt);            // 65536 threads
    cd_scan<<<NGRIDS, 1024>>>();                 // 8 blocks
    cd_scatter<<<64, 1024>>>(pred, gt);          // 65536 threads
    cd_query<<<NQ / 256, 256>>>();               // 256 blocks x 256, sorted order
    cd_reduce<<<1, 1024>>>(out);
}